// round 1
// baseline (speedup 1.0000x reference)
#include <cuda_runtime.h>
#include <math.h>

// Problem dims
constexpr int Bn  = 64;
constexpr int Cn  = 512;
constexpr int Sn  = 512;
constexpr int En  = 257;   // rfft length
constexpr int LKn = 128;
constexpr int HKn = 129;
constexpr int Rn  = Bn * Cn;  // 32768 rows (b,c) flattened

// ---------------- scratch (device globals; no allocations allowed) ----------
__device__ float g_Wr[Sn * En];   // forward DFT basis  [s][e]
__device__ float g_Wi[Sn * En];
__device__ float g_Vr[En * Sn];   // inverse basis      [e][s]
__device__ float g_Vi[En * Sn];
__device__ float g_Fr[Rn * En];   // rfft(x)
__device__ float g_Fi[Rn * En];
__device__ float g_Lr[Rn * En];   // low  = crelu(F[:, :128] @ l1 + lb1)
__device__ float g_Li[Rn * En];
__device__ float g_Hr[Rn * En];   // high = crelu(F[:, 128:] @ h1 + hb1)
__device__ float g_Hi[Rn * En];
__device__ float g_S1r[Bn * Cn * Cn];  // scores1 -> becomes P (softmax sum)
__device__ float g_S1i[Bn * Cn * Cn];
__device__ float g_S2r[Bn * Cn * Cn];  // scores2
__device__ float g_S2i[Bn * Cn * Cn];
__device__ float g_Or[Rn * En];   // attention output (pre-irfft)
__device__ float g_Oi[Rn * En];

// ---------------- twiddle init ----------------------------------------------
__global__ void k_twiddle() {
    int idx = blockIdx.x * blockDim.x + threadIdx.x;
    if (idx >= Sn * En) return;
    const float sc0 = 0.044194173824159216f;  // 1/sqrt(512)
    {   // forward: W[s][e] = exp(-2*pi*i*s*e/S)/sqrt(S)
        int s = idx / En, e = idx - s * En;
        int t = (s * e) & (Sn - 1);           // exact mod-512 reduction
        float sv, cv;
        sincospif(2.0f * (float)t / (float)Sn, &sv, &cv);
        g_Wr[idx] = cv * sc0;
        g_Wi[idx] = -sv * sc0;
    }
    {   // inverse (Hermitian folded): out[s] = sum_e Or*Vr + Oi*Vi
        int e = idx / Sn, s = idx - e * Sn;
        int t = (s * e) & (Sn - 1);
        float sv, cv;
        sincospif(2.0f * (float)t / (float)Sn, &sv, &cv);
        float ce = (e == 0 || e == En - 1) ? 1.0f : 2.0f;
        g_Vr[idx] = cv * ce * sc0;
        g_Vi[idx] = -sv * ce * sc0;
    }
}

// ---------------- rfft GEMM: (Fr,Fi) = x(32768x512) @ (Wr,Wi)(512x257) ------
__global__ void __launch_bounds__(256)
k_rfft(const float* __restrict__ x,
       const float* __restrict__ Wr, const float* __restrict__ Wi,
       float* __restrict__ Fr, float* __restrict__ Fi) {
    __shared__ __align__(16) float As[16][68];
    __shared__ __align__(16) float B1s[16][68];
    __shared__ __align__(16) float B2s[16][68];
    const int tid = threadIdx.x;
    const int tx = tid & 15, ty = tid >> 4;
    const int m0 = blockIdx.y * 64, n0 = blockIdx.x * 64;
    const int nl = tid & 63, kq = tid >> 6;
    float c1[4][4] = {}, c2[4][4] = {};

    for (int k0 = 0; k0 < Sn; k0 += 16) {
#pragma unroll
        for (int i = 0; i < 4; i++) {
            int m = ty + i * 16;
            As[tx][m] = x[(long)(m0 + m) * Sn + k0 + tx];
        }
#pragma unroll
        for (int i = 0; i < 4; i++) {
            int k = kq + i * 4;
            int gn = n0 + nl;
            float b1 = 0.f, b2 = 0.f;
            if (gn < En) { long o = (long)(k0 + k) * En + gn; b1 = Wr[o]; b2 = Wi[o]; }
            B1s[k][nl] = b1; B2s[k][nl] = b2;
        }
        __syncthreads();
#pragma unroll
        for (int k = 0; k < 16; k++) {
            float4 a  = *(const float4*)&As[k][ty * 4];
            float4 b1 = *(const float4*)&B1s[k][tx * 4];
            float4 b2 = *(const float4*)&B2s[k][tx * 4];
            float av[4]  = {a.x, a.y, a.z, a.w};
            float b1v[4] = {b1.x, b1.y, b1.z, b1.w};
            float b2v[4] = {b2.x, b2.y, b2.z, b2.w};
#pragma unroll
            for (int i = 0; i < 4; i++)
#pragma unroll
                for (int j = 0; j < 4; j++) {
                    c1[i][j] = fmaf(av[i], b1v[j], c1[i][j]);
                    c2[i][j] = fmaf(av[i], b2v[j], c2[i][j]);
                }
        }
        __syncthreads();
    }
#pragma unroll
    for (int i = 0; i < 4; i++) {
        int gm = m0 + ty * 4 + i;
#pragma unroll
        for (int j = 0; j < 4; j++) {
            int gn = n0 + tx * 4 + j;
            if (gn < En) {
                long o = (long)gm * En + gn;
                Fr[o] = c1[i][j];
                Fi[o] = c2[i][j];
            }
        }
    }
}

// ---------------- generic complex NN GEMM (+bias +relu, batched) ------------
__global__ void __launch_bounds__(256)
k_cgemm_nn(const float* __restrict__ Ar, const float* __restrict__ Ai, int lda, long aStr,
           const float* __restrict__ Br, const float* __restrict__ Bi, int ldb, long bStr,
           float* __restrict__ Cr, float* __restrict__ Ci, int ldc, long cStr,
           int N, int K,
           const float* __restrict__ biasR, const float* __restrict__ biasI, int doRelu) {
    const long bz = blockIdx.z;
    Ar += bz * aStr; Ai += bz * aStr;
    Br += bz * bStr; Bi += bz * bStr;
    Cr += bz * cStr; Ci += bz * cStr;

    __shared__ __align__(16) float Asr[16][68], Asi[16][68];
    __shared__ __align__(16) float Bsr[16][68], Bsi[16][68];
    const int tid = threadIdx.x;
    const int tx = tid & 15, ty = tid >> 4;
    const int m0 = blockIdx.y * 64, n0 = blockIdx.x * 64;
    const int nl = tid & 63, kq = tid >> 6;
    float cr[4][4] = {}, cim[4][4] = {};

    for (int k0 = 0; k0 < K; k0 += 16) {
#pragma unroll
        for (int i = 0; i < 4; i++) {
            int m = ty + i * 16;
            int gk = k0 + tx;
            float ar = 0.f, ai = 0.f;
            if (gk < K) { long o = (long)(m0 + m) * lda + gk; ar = Ar[o]; ai = Ai[o]; }
            Asr[tx][m] = ar; Asi[tx][m] = ai;
        }
#pragma unroll
        for (int i = 0; i < 4; i++) {
            int k = kq + i * 4;
            int gk = k0 + k, gn = n0 + nl;
            float br = 0.f, bi = 0.f;
            if (gk < K && gn < N) { long o = (long)gk * ldb + gn; br = Br[o]; bi = Bi[o]; }
            Bsr[k][nl] = br; Bsi[k][nl] = bi;
        }
        __syncthreads();
#pragma unroll
        for (int k = 0; k < 16; k++) {
            float4 a_r = *(const float4*)&Asr[k][ty * 4];
            float4 a_i = *(const float4*)&Asi[k][ty * 4];
            float4 b_r = *(const float4*)&Bsr[k][tx * 4];
            float4 b_i = *(const float4*)&Bsi[k][tx * 4];
            float arv[4] = {a_r.x, a_r.y, a_r.z, a_r.w};
            float aiv[4] = {a_i.x, a_i.y, a_i.z, a_i.w};
            float brv[4] = {b_r.x, b_r.y, b_r.z, b_r.w};
            float biv[4] = {b_i.x, b_i.y, b_i.z, b_i.w};
#pragma unroll
            for (int i = 0; i < 4; i++)
#pragma unroll
                for (int j = 0; j < 4; j++) {
                    cr[i][j]  = fmaf(arv[i],  brv[j], cr[i][j]);
                    cr[i][j]  = fmaf(-aiv[i], biv[j], cr[i][j]);
                    cim[i][j] = fmaf(arv[i],  biv[j], cim[i][j]);
                    cim[i][j] = fmaf(aiv[i],  brv[j], cim[i][j]);
                }
        }
        __syncthreads();
    }
#pragma unroll
    for (int i = 0; i < 4; i++) {
        int gm = m0 + ty * 4 + i;
#pragma unroll
        for (int j = 0; j < 4; j++) {
            int gn = n0 + tx * 4 + j;
            if (gn < N) {
                float vr = cr[i][j], vi = cim[i][j];
                if (biasR) { vr += biasR[gn]; vi += biasI[gn]; }
                if (doRelu) { vr = fmaxf(vr, 0.f); vi = fmaxf(vi, 0.f); }
                long o = (long)gm * ldc + gn;
                Cr[o] = vr; Ci[o] = vi;
            }
        }
    }
}

// ---------------- complex NT GEMM (scores), batched over blockIdx.z ---------
__global__ void __launch_bounds__(256)
k_cgemm_nt(const float* __restrict__ Ar, const float* __restrict__ Ai,
           const float* __restrict__ Br, const float* __restrict__ Bi,
           float* __restrict__ Cr, float* __restrict__ Ci, float scale) {
    const long aoff = (long)blockIdx.z * Cn * En;
    const long coff = (long)blockIdx.z * Cn * Cn;
    Ar += aoff; Ai += aoff; Br += aoff; Bi += aoff;
    Cr += coff; Ci += coff;

    __shared__ __align__(16) float Asr[16][68], Asi[16][68];
    __shared__ __align__(16) float Bsr[16][68], Bsi[16][68];
    const int tid = threadIdx.x;
    const int tx = tid & 15, ty = tid >> 4;
    const int m0 = blockIdx.y * 64, n0 = blockIdx.x * 64;
    float cr[4][4] = {}, cim[4][4] = {};

    for (int k0 = 0; k0 < En; k0 += 16) {
#pragma unroll
        for (int i = 0; i < 4; i++) {
            int m = ty + i * 16;
            int gk = k0 + tx;
            float ar = 0.f, ai = 0.f;
            if (gk < En) { long o = (long)(m0 + m) * En + gk; ar = Ar[o]; ai = Ai[o]; }
            Asr[tx][m] = ar; Asi[tx][m] = ai;
        }
#pragma unroll
        for (int i = 0; i < 4; i++) {
            int n = ty + i * 16;
            int gk = k0 + tx;
            float br = 0.f, bi = 0.f;
            if (gk < En) { long o = (long)(n0 + n) * En + gk; br = Br[o]; bi = Bi[o]; }
            Bsr[tx][n] = br; Bsi[tx][n] = bi;
        }
        __syncthreads();
#pragma unroll
        for (int k = 0; k < 16; k++) {
            float4 a_r = *(const float4*)&Asr[k][ty * 4];
            float4 a_i = *(const float4*)&Asi[k][ty * 4];
            float4 b_r = *(const float4*)&Bsr[k][tx * 4];
            float4 b_i = *(const float4*)&Bsi[k][tx * 4];
            float arv[4] = {a_r.x, a_r.y, a_r.z, a_r.w};
            float aiv[4] = {a_i.x, a_i.y, a_i.z, a_i.w};
            float brv[4] = {b_r.x, b_r.y, b_r.z, b_r.w};
            float biv[4] = {b_i.x, b_i.y, b_i.z, b_i.w};
#pragma unroll
            for (int i = 0; i < 4; i++)
#pragma unroll
                for (int j = 0; j < 4; j++) {
                    cr[i][j]  = fmaf(arv[i],  brv[j], cr[i][j]);
                    cr[i][j]  = fmaf(-aiv[i], biv[j], cr[i][j]);
                    cim[i][j] = fmaf(arv[i],  biv[j], cim[i][j]);
                    cim[i][j] = fmaf(aiv[i],  brv[j], cim[i][j]);
                }
        }
        __syncthreads();
    }
#pragma unroll
    for (int i = 0; i < 4; i++) {
        int gm = m0 + ty * 4 + i;
#pragma unroll
        for (int j = 0; j < 4; j++) {
            int gn = n0 + tx * 4 + j;
            long o = (long)gm * Cn + gn;
            Cr[o] = scale * cr[i][j];
            Ci[o] = scale * cim[i][j];
        }
    }
}

// ---------------- softmax combine: P = softmax(S1) + softmax(S2), in place --
__global__ void k_softmax(float* __restrict__ S1r, float* __restrict__ S1i,
                          const float* __restrict__ S2r, const float* __restrict__ S2i) {
    __shared__ float2 sh[256];
    const long base = (long)blockIdx.x * Cn;
    const int t = threadIdx.x;

#pragma unroll
    for (int part = 0; part < 2; part++) {
        float* dst        = part ? S1i : S1r;
        const float* src1 = part ? S1i : S1r;
        const float* src2 = part ? S2i : S2r;
        float v1a = src1[base + t], v1b = src1[base + t + 256];
        float v2a = src2[base + t], v2b = src2[base + t + 256];

        sh[t] = make_float2(fmaxf(v1a, v1b), fmaxf(v2a, v2b));
        __syncthreads();
        for (int s = 128; s > 0; s >>= 1) {
            if (t < s) {
                float2 o = sh[t + s];
                sh[t].x = fmaxf(sh[t].x, o.x);
                sh[t].y = fmaxf(sh[t].y, o.y);
            }
            __syncthreads();
        }
        float m1 = sh[0].x, m2 = sh[0].y;
        __syncthreads();

        float e1a = expf(v1a - m1), e1b = expf(v1b - m1);
        float e2a = expf(v2a - m2), e2b = expf(v2b - m2);
        sh[t] = make_float2(e1a + e1b, e2a + e2b);
        __syncthreads();
        for (int s = 128; s > 0; s >>= 1) {
            if (t < s) {
                float2 o = sh[t + s];
                sh[t].x += o.x;
                sh[t].y += o.y;
            }
            __syncthreads();
        }
        float r1 = 1.f / sh[0].x, r2 = 1.f / sh[0].y;
        __syncthreads();

        dst[base + t]       = e1a * r1 + e2a * r2;
        dst[base + t + 256] = e1b * r1 + e2b * r2;
    }
}

// ---------------- irfft GEMM: out = Or@Vr + Oi@Vi ---------------------------
__global__ void __launch_bounds__(256)
k_irfft(const float* __restrict__ Ar, const float* __restrict__ Ai,
        const float* __restrict__ B1, const float* __restrict__ B2,
        float* __restrict__ out) {
    __shared__ __align__(16) float Asr[16][68], Asi[16][68];
    __shared__ __align__(16) float B1s[16][68], B2s[16][68];
    const int tid = threadIdx.x;
    const int tx = tid & 15, ty = tid >> 4;
    const int m0 = blockIdx.y * 64, n0 = blockIdx.x * 64;
    const int nl = tid & 63, kq = tid >> 6;
    float c[4][4] = {};

    for (int k0 = 0; k0 < En; k0 += 16) {
#pragma unroll
        for (int i = 0; i < 4; i++) {
            int m = ty + i * 16;
            int gk = k0 + tx;
            float ar = 0.f, ai = 0.f;
            if (gk < En) { long o = (long)(m0 + m) * En + gk; ar = Ar[o]; ai = Ai[o]; }
            Asr[tx][m] = ar; Asi[tx][m] = ai;
        }
#pragma unroll
        for (int i = 0; i < 4; i++) {
            int k = kq + i * 4;
            int gk = k0 + k, gn = n0 + nl;
            float b1 = 0.f, b2 = 0.f;
            if (gk < En) { long o = (long)gk * Sn + gn; b1 = B1[o]; b2 = B2[o]; }
            B1s[k][nl] = b1; B2s[k][nl] = b2;
        }
        __syncthreads();
#pragma unroll
        for (int k = 0; k < 16; k++) {
            float4 a_r = *(const float4*)&Asr[k][ty * 4];
            float4 a_i = *(const float4*)&Asi[k][ty * 4];
            float4 b_1 = *(const float4*)&B1s[k][tx * 4];
            float4 b_2 = *(const float4*)&B2s[k][tx * 4];
            float arv[4] = {a_r.x, a_r.y, a_r.z, a_r.w};
            float aiv[4] = {a_i.x, a_i.y, a_i.z, a_i.w};
            float b1v[4] = {b_1.x, b_1.y, b_1.z, b_1.w};
            float b2v[4] = {b_2.x, b_2.y, b_2.z, b_2.w};
#pragma unroll
            for (int i = 0; i < 4; i++)
#pragma unroll
                for (int j = 0; j < 4; j++) {
                    c[i][j] = fmaf(arv[i], b1v[j], c[i][j]);
                    c[i][j] = fmaf(aiv[i], b2v[j], c[i][j]);
                }
        }
        __syncthreads();
    }
#pragma unroll
    for (int i = 0; i < 4; i++) {
        int gm = m0 + ty * 4 + i;
#pragma unroll
        for (int j = 0; j < 4; j++) {
            int gn = n0 + tx * 4 + j;
            out[(long)gm * Sn + gn] = c[i][j];
        }
    }
}

// ---------------- launch ----------------------------------------------------
extern "C" void kernel_launch(void* const* d_in, const int* in_sizes, int n_in,
                              void* d_out, int out_size) {
    const float* x    = (const float*)d_in[0];
    const float* l1r  = (const float*)d_in[1];
    const float* l1i  = (const float*)d_in[2];
    const float* h1r  = (const float*)d_in[3];
    const float* h1i  = (const float*)d_in[4];
    const float* lb1r = (const float*)d_in[5];
    const float* lb1i = (const float*)d_in[6];
    const float* hb1r = (const float*)d_in[7];
    const float* hb1i = (const float*)d_in[8];
    float* out = (float*)d_out;

    float *Wr, *Wi, *Vr, *Vi, *Fr, *Fi, *Lr, *Li, *Hr, *Hi;
    float *S1r, *S1i, *S2r, *S2i, *Or, *Oi;
    cudaGetSymbolAddress((void**)&Wr, g_Wr);
    cudaGetSymbolAddress((void**)&Wi, g_Wi);
    cudaGetSymbolAddress((void**)&Vr, g_Vr);
    cudaGetSymbolAddress((void**)&Vi, g_Vi);
    cudaGetSymbolAddress((void**)&Fr, g_Fr);
    cudaGetSymbolAddress((void**)&Fi, g_Fi);
    cudaGetSymbolAddress((void**)&Lr, g_Lr);
    cudaGetSymbolAddress((void**)&Li, g_Li);
    cudaGetSymbolAddress((void**)&Hr, g_Hr);
    cudaGetSymbolAddress((void**)&Hi, g_Hi);
    cudaGetSymbolAddress((void**)&S1r, g_S1r);
    cudaGetSymbolAddress((void**)&S1i, g_S1i);
    cudaGetSymbolAddress((void**)&S2r, g_S2r);
    cudaGetSymbolAddress((void**)&S2i, g_S2i);
    cudaGetSymbolAddress((void**)&Or, g_Or);
    cudaGetSymbolAddress((void**)&Oi, g_Oi);

    const float scale = 1.0f / sqrtf((float)En);

    // 1. DFT bases
    k_twiddle<<<(Sn * En + 255) / 256, 256>>>();

    // 2. rfft
    k_rfft<<<dim3(5, Rn / 64), 256>>>(x, Wr, Wi, Fr, Fi);

    // 3. low / high band complex linear + bias + crelu
    k_cgemm_nn<<<dim3(5, Rn / 64), 256>>>(Fr, Fi, En, 0, l1r, l1i, En, 0,
                                          Lr, Li, En, 0, En, LKn, lb1r, lb1i, 1);
    k_cgemm_nn<<<dim3(5, Rn / 64), 256>>>(Fr + LKn, Fi + LKn, En, 0, h1r, h1i, En, 0,
                                          Hr, Hi, En, 0, En, HKn, hb1r, hb1i, 1);

    // 4. scores: S1 = scale * L @ L^T, S2 = scale * L @ H^T (batched over B)
    k_cgemm_nt<<<dim3(8, 8, Bn), 256>>>(Lr, Li, Lr, Li, S1r, S1i, scale);
    k_cgemm_nt<<<dim3(8, 8, Bn), 256>>>(Lr, Li, Hr, Hi, S2r, S2i, scale);

    // 5. P = softmax(S1) + softmax(S2) (per real/imag plane, in place -> S1)
    k_softmax<<<Rn, 256>>>(S1r, S1i, S2r, S2i);

    // 6. O = P @ L (complex, batched)
    k_cgemm_nn<<<dim3(5, 8, Bn), 256>>>(S1r, S1i, Cn, (long)Cn * Cn,
                                        Lr, Li, En, (long)Cn * En,
                                        Or, Oi, En, (long)Cn * En,
                                        En, Cn, nullptr, nullptr, 0);

    // 7. irfft -> output
    k_irfft<<<dim3(8, Rn / 64), 256>>>(Or, Oi, Vr, Vi, out);
}